// round 1
// baseline (speedup 1.0000x reference)
#include <cuda_runtime.h>
#include <cuda_bf16.h>

// SoftMSMLoss: soft Move-Split-Merge DP, gamma=1, c=1, 512x512 per batch, B=64.
// Anti-diagonal wavefront, one block per batch element, thread t owns row i=t.

#define TLEN 512
#define NDIAG (2 * TLEN - 1)
#define NBATCH 64

__device__ float g_costs[NBATCH];

__global__ __launch_bounds__(TLEN, 1) void soft_msm_kernel(
    const float* __restrict__ x, const float* __restrict__ y) {
    __shared__ float sx[TLEN];
    __shared__ float sy[TLEN];
    __shared__ float sEb[TLEN];   // exp(-(y_j - y_{j-1})^2)
    __shared__ float sDyb[TLEN];  // y_j - y_{j-1}
    __shared__ float bufA[TLEN], bufB[TLEN], bufC[TLEN];

    const int t = threadIdx.x;
    const int b = blockIdx.x;

    const float myXi = x[b * TLEN + t];
    const float yloc = y[b * TLEN + t];
    sx[t] = myXi;
    sy[t] = yloc;
    __syncthreads();

    // Per-row constants (for the "up" transition): a = x_i - x_{i-1}
    float myDxa = 0.0f, myEa = 0.0f;
    if (t > 0) {
        myDxa = myXi - sx[t - 1];
        myEa = __expf(-myDxa * myDxa);
    }
    // Per-column constants (for the "left" transition): a = y_j - y_{j-1}
    float dyb = 0.0f, eb = 0.0f;
    if (t > 0) {
        dyb = yloc - sy[t - 1];
        eb = __expf(-dyb * dyb);
    }
    sDyb[t] = dyb;
    sEb[t] = eb;
    __syncthreads();

    float* prev2 = bufA;  // diagonal d-2
    float* prev1 = bufB;  // diagonal d-1
    float* cur = bufC;    // diagonal d
    float myPrev = 0.0f;  // this thread's C[i][j-1] (its own cell on prev diagonal)

    for (int d = 0; d < NDIAG; ++d) {
        const int j = d - t;
        if (j >= 0 && j < TLEN) {
            const float yj = sy[j];
            const float bm = myXi - yj;          // b for "up"; -(b) for "left"
            const float match = bm * bm;          // shared b^2 for both transitions
            const float Em = __expf(-match);

            float cij;
            if (t == 0) {
                if (j == 0) {
                    cij = match;  // C[0][0]
                } else {
                    // row 0: C[0][j] = C[0][j-1] + left
                    const float a = sDyb[j];
                    const float u = -a * bm;  // a * (y_j - x_i)
                    const float w = 0.5f + 0.5f * u * rsqrtf(u * u + 1e-9f);
                    const float left = 1.0f - w * __logf(sEb[j] + Em);
                    cij = myPrev + left;
                }
            } else if (j == 0) {
                // col 0: C[i][0] = C[i-1][0] + up
                const float u = myDxa * bm;
                const float w = 0.5f + 0.5f * u * rsqrtf(u * u + 1e-9f);
                const float up = 1.0f - w * __logf(myEa + Em);
                cij = prev1[t - 1] + up;
            } else {
                // up transition
                const float uu = myDxa * bm;
                const float wu = 0.5f + 0.5f * uu * rsqrtf(uu * uu + 1e-9f);
                const float up = 1.0f - wu * __logf(myEa + Em);
                // left transition
                const float a = sDyb[j];
                const float ul = -a * bm;
                const float wl = 0.5f + 0.5f * ul * rsqrtf(ul * ul + 1e-9f);
                const float left = 1.0f - wl * __logf(sEb[j] + Em);

                const float dd = prev2[t - 1] + match;
                const float du = prev1[t - 1] + up;
                const float dl = myPrev + left;
                const float m = fminf(dd, fminf(du, dl));
                const float s = __expf(m - dd) + __expf(m - du) + __expf(m - dl);
                cij = m - __logf(s);
            }
            cur[t] = cij;
            myPrev = cij;
        }
        __syncthreads();
        float* tmp = prev2;
        prev2 = prev1;
        prev1 = cur;
        cur = tmp;
    }

    if (t == TLEN - 1) g_costs[b] = myPrev;  // C[511][511]
}

__global__ void soft_msm_reduce_kernel(float* __restrict__ out) {
    const int t = threadIdx.x;  // 32 threads
    float v = g_costs[t] + g_costs[t + 32];
#pragma unroll
    for (int o = 16; o > 0; o >>= 1) v += __shfl_down_sync(0xffffffffu, v, o);
    if (t == 0) out[0] = v * (1.0f / (float)NBATCH);
}

extern "C" void kernel_launch(void* const* d_in, const int* in_sizes, int n_in,
                              void* d_out, int out_size) {
    const float* x = (const float*)d_in[0];
    const float* y = (const float*)d_in[1];
    float* out = (float*)d_out;
    soft_msm_kernel<<<NBATCH, TLEN>>>(x, y);
    soft_msm_reduce_kernel<<<1, 32>>>(out);
}

// round 2
// speedup vs baseline: 1.1587x; 1.1587x over previous
#include <cuda_runtime.h>
#include <cuda_bf16.h>

// SoftMSMLoss: soft Move-Split-Merge DP, gamma=1, c=1, 512x512 per batch, B=64.
// Warp-shuffle pipelined wavefront: each warp owns a 32-row band, lanes skewed
// along the anti-diagonal; inter-band handoff via SMEM ring + release/acquire
// flags. No __syncthreads in the inner loop.

#define TLEN 512
#define NWARP 16
#define NBATCH 64
#define CHUNK 16

__device__ float g_costs[NBATCH];

__global__ __launch_bounds__(512, 1) void soft_msm_kernel(
    const float* __restrict__ x, const float* __restrict__ y) {
    __shared__ float4 scol[TLEN];            // {y_j, dyb_j, eb_j, pad}
    __shared__ float hand[NWARP - 1][TLEN];  // band-boundary row values
    __shared__ volatile int flags[NWARP - 1];
    __shared__ float sx[TLEN];

    const int t = threadIdx.x;
    const int w = t >> 5;
    const int l = t & 31;
    const int b = blockIdx.x;

    const float xi = x[b * TLEN + t];
    const float yown = y[b * TLEN + t];
    sx[t] = xi;
    scol[t].x = yown;
    if (t < NWARP - 1) flags[t] = 0;
    __syncthreads();

    // per-row constants: a_up = x_i - x_{i-1}
    float myDxa = 0.0f, myEa = 0.0f;
    if (t > 0) {
        myDxa = xi - sx[t - 1];
        myEa = __expf(-myDxa * myDxa);
    }
    // per-column constants: a_left = y_j - y_{j-1}
    float ym1 = (t > 0) ? scol[t - 1].x : 0.0f;
    __syncthreads();
    {
        float dyb = 0.0f, eb = 0.0f;
        if (t > 0) {
            dyb = yown - ym1;
            eb = __expf(-dyb * dyb);
        }
        scol[t] = make_float4(yown, dyb, eb, 0.0f);
    }
    __syncthreads();

    float cij = 0.0f;     // own value at (i, j-1) -> becomes (i, j)
    float upPrev = 0.0f;  // up-neighbor value one step ago = C(i-1, j-1)

    for (int s = 0; s < TLEN + 31; ++s) {
        // acquire: warp w's lane 0 consumes hand[w-1][s .. s+CHUNK-1]
        if (w > 0 && s < TLEN && (s & (CHUNK - 1)) == 0) {
            const int need = (s + CHUNK < TLEN) ? (s + CHUNK) : TLEN;
            while (flags[w - 1] < need) __nanosleep(32);
            __threadfence_block();
        }

        float up = __shfl_up_sync(0xffffffffu, cij, 1);  // C(i-1, j)
        const int j = s - l;
        const bool active = (j >= 0) & (j < TLEN);
        if (l == 0 && w > 0 && active) up = hand[w - 1][j];
        const float diag = upPrev;  // C(i-1, j-1)
        upPrev = up;

        if (active) {
            const float4 cv = scol[j];
            const float bm = xi - cv.x;  // x_i - y_j
            const float match = bm * bm;
            const float Em = __expf(-match);
            float cnew;
            if (t == 0) {
                if (j == 0) {
                    cnew = match;
                } else {
                    const float ul = -cv.y * bm;
                    const float wl = 0.5f + 0.5f * ul * rsqrtf(ul * ul + 1e-9f);
                    const float leftc = 1.0f - wl * __logf(cv.z + Em);
                    cnew = cij + leftc;
                }
            } else {
                const float uu = myDxa * bm;
                const float wu = 0.5f + 0.5f * uu * rsqrtf(uu * uu + 1e-9f);
                const float upc = 1.0f - wu * __logf(myEa + Em);
                if (j == 0) {
                    cnew = up + upc;
                } else {
                    const float ul = -cv.y * bm;
                    const float wl = 0.5f + 0.5f * ul * rsqrtf(ul * ul + 1e-9f);
                    const float leftc = 1.0f - wl * __logf(cv.z + Em);
                    const float dd = diag + match;
                    const float du = up + upc;
                    const float dl = cij + leftc;
                    const float m = fminf(dd, fminf(du, dl));
                    const float ssum =
                        __expf(m - dd) + __expf(m - du) + __expf(m - dl);
                    cnew = m - __logf(ssum);
                }
            }
            cij = cnew;
            if (l == 31 && w < NWARP - 1) hand[w][j] = cij;
            // release: publish completed chunk of boundary row
            if (l == 31 && w < NWARP - 1 && (j & (CHUNK - 1)) == CHUNK - 1) {
                __threadfence_block();
                flags[w] = j + 1;
            }
        }
    }

    if (t == TLEN - 1) g_costs[b] = cij;  // C[511][511]
}

__global__ void soft_msm_reduce_kernel(float* __restrict__ out) {
    const int t = threadIdx.x;  // 32 threads
    float v = g_costs[t] + g_costs[t + 32];
#pragma unroll
    for (int o = 16; o > 0; o >>= 1) v += __shfl_down_sync(0xffffffffu, v, o);
    if (t == 0) out[0] = v * (1.0f / (float)NBATCH);
}

extern "C" void kernel_launch(void* const* d_in, const int* in_sizes, int n_in,
                              void* d_out, int out_size) {
    const float* x = (const float*)d_in[0];
    const float* y = (const float*)d_in[1];
    float* out = (float*)d_out;
    soft_msm_kernel<<<NBATCH, 512>>>(x, y);
    soft_msm_reduce_kernel<<<1, 32>>>(out);
}

// round 4
// speedup vs baseline: 2.3727x; 2.0477x over previous
#include <cuda_runtime.h>
#include <cuda_bf16.h>

// SoftMSMLoss: soft-MSM DP, gamma=1, c=1, 512x512 per batch, B=64.
// Branch-free warp-pipelined anti-diagonal wavefront + fused mean reduction.

#define TLEN 512
#define NWARP 16
#define NBATCH 64
#define CHUNK 8
#define NSTEP 544  // 68 * 8; covers s = 0..542 needed, +1 harmless pad
#define BIG 1e30f

__device__ float g_costs[NBATCH];
__device__ int g_done;  // zero-initialized; reset by the reducing block

__global__ __launch_bounds__(512, 1) void soft_msm_kernel(
    const float* __restrict__ x, const float* __restrict__ y,
    float* __restrict__ out) {
    __shared__ float4 scol[TLEN];            // {y_j, dyb_j, eb_j, pad}
    __shared__ float hand[NWARP - 1][TLEN];  // band-boundary row values
    __shared__ volatile int flags[NWARP - 1];
    __shared__ float sx[TLEN];

    const int t = threadIdx.x;
    const int w = t >> 5;
    const int l = t & 31;
    const int b = blockIdx.x;

    const float xi = x[b * TLEN + t];
    const float yown = y[b * TLEN + t];
    sx[t] = xi;
    scol[t].x = yown;
    if (t < NWARP - 1) flags[t] = 0;
    __syncthreads();

    // per-row constants (up transition): a = x_i - x_{i-1}; t==0 -> 0 sentinels
    float myDxa = 0.0f, myEa = 0.0f;
    if (t > 0) {
        myDxa = xi - sx[t - 1];
        myEa = __expf(-myDxa * myDxa);
    }
    const float ym1 = (t > 0) ? scol[t - 1].x : yown;
    __syncthreads();
    {
        const float dyb = yown - ym1;  // 0 for t==0
        scol[t] = make_float4(yown, dyb, (t > 0) ? __expf(-dyb * dyb) : 0.0f,
                              0.0f);
    }
    __syncthreads();

    float cij = BIG;                              // C(i, j-1); BIG = "no cell"
    float upPrev = (t == 0) ? 0.0f : BIG;         // becomes diag = C(i-1,j-1)
    const bool isConsumer = (l == 0) && (w > 0);  // reads hand[w-1]
    const bool isProducer = (l == 31) && (w < NWARP - 1);
    const bool isT0 = (t == 0);

#pragma unroll 8
    for (int s = 0; s < NSTEP; ++s) {
        if (w > 0 && s < TLEN && (s & (CHUNK - 1)) == 0) {
            const int need = (s + CHUNK < TLEN) ? (s + CHUNK) : TLEN;
            while (flags[w - 1] < need) __nanosleep(20);
            __threadfence_block();
        }

        float up = __shfl_up_sync(0xffffffffu, cij, 1);  // C(i-1, j)
        const int j = s - l;
        const bool active = ((unsigned)j < (unsigned)TLEN);
        const int jc = active ? j : 0;
        if (isT0) up = BIG;
        if (isConsumer) up = hand[w - 1][jc];
        const float diag = upPrev;  // C(i-1, j-1)
        upPrev = up;

        const float4 cv = scol[jc];
        const float bm = xi - cv.x;
        const float match = bm * bm;
        const float Em = __expf(-match);

        const float uu = myDxa * bm;
        const float wu = 0.5f + 0.5f * uu * rsqrtf(uu * uu + 1e-9f);
        const float upc = 1.0f - wu * __logf(myEa + Em);

        const float ul = -cv.y * bm;
        const float wl = 0.5f + 0.5f * ul * rsqrtf(ul * ul + 1e-9f);
        const float leftc = 1.0f - wl * __logf(cv.z + Em);

        const float dd = diag + match;
        const float du = up + upc;
        const float dl = cij + leftc;
        const float m = fminf(dd, fminf(du, dl));
        const float ssum = __expf(m - dd) + __expf(m - du) + __expf(m - dl);
        const float cnew = m - __logf(ssum);
        cij = active ? cnew : cij;

        if (isProducer) hand[w][jc] = cij;  // stale pre-fill writes harmless
        if (isProducer && ((j & (CHUNK - 1)) == CHUNK - 1)) {
            __threadfence_block();
            flags[w] = j + 1;
        }
    }

    if (t == TLEN - 1) {
        g_costs[b] = cij;  // C[511][511]
        __threadfence();
        const int old = atomicAdd(&g_done, 1);
        if (old == NBATCH - 1) {
            __threadfence();
            float v = 0.0f;
#pragma unroll
            for (int i = 0; i < NBATCH; ++i) v += g_costs[i];
            out[0] = v * (1.0f / (float)NBATCH);
            atomicExch(&g_done, 0);  // ready for next graph replay
        }
    }
}

extern "C" void kernel_launch(void* const* d_in, const int* in_sizes, int n_in,
                              void* d_out, int out_size) {
    const float* x = (const float*)d_in[0];
    const float* y = (const float*)d_in[1];
    float* out = (float*)d_out;
    soft_msm_kernel<<<NBATCH, TLEN>>>(x, y, out);
}